// round 6
// baseline (speedup 1.0000x reference)
#include <cuda_runtime.h>

// RFCM loss — fused single kernel, v5.
// z-sum-first separable stencil, k split over threadIdx.z, single-wave grid,
// depth-2 z prefetch, 1 barrier per plane (double-buffered smem by z parity).
// J1 = (1/N)*sum_{b,k}(C - A^2/B);  J2 voxel = M*(S27-M) - sum_k mem_k*(s27_k-mem_k)

#define FULLMASK 0xffffffffu

__device__ double g_acc[25];
__device__ unsigned int g_sem;

__device__ __forceinline__ float4 sq4(float4 p) {
    float4 m; m.x=p.x*p.x; m.y=p.y*p.y; m.z=p.z*p.z; m.w=p.w*p.w; return m;
}
__device__ __forceinline__ float4 add4(float4 a, float4 b) {
    float4 r; r.x=a.x+b.x; r.y=a.y+b.y; r.z=a.z+b.z; r.w=a.w+b.w; return r;
}

// dynamic smem: s_xs [slot2][k4][row10][32]f4 , s_ex [slot2][grp2][ty8][32]f4 , s_red
#define XS_F4 (2*4*10*32)
#define EX_F4 (2*2*8*32)
#define SMEM_BYTES ((XS_F4 + EX_F4)*16 + 16*8*4)

__global__ __launch_bounds__(512, 2)
void rfcm_kernel(const float* __restrict__ ypred, const float* __restrict__ image,
                 float* __restrict__ out) {
    extern __shared__ float4 smem4[];
    float4* s_xs = smem4;                 // ((slot*4+k)*10+row)*32+tx
    float4* s_ex = smem4 + XS_F4;         // ((slot*2+grp)*8+ty)*32+tx
    float*  s_red = (float*)(smem4 + XS_F4 + EX_F4);

    const int tx = threadIdx.x;           // x quad
    const int ty = threadIdx.y;           // y row 0..7
    const int tk = threadIdx.z;           // k group
    const int tid = tx + 32*ty + 256*tk;
    const int wid = ty + 8*tk;
    const int y0 = blockIdx.x * 8;
    const int z0 = blockIdx.y * 16;
    const int b  = blockIdx.z;
    const int gy = y0 + ty;

    const float* yp_b = ypred + (size_t)b * 4 * 128 * 16384;
    const float* im_b = image + (size_t)b * 128 * 16384;

    auto ldsq = [&](int k, int zz, int yy) -> float4 {
        float4 p = make_float4(0.f,0.f,0.f,0.f);
        if ((unsigned)zz < 128u && (unsigned)yy < 128u)
            p = *(const float4*)(yp_b + (((size_t)(k*128+zz))<<14) + (yy<<7) + (tx<<2));
        return sq4(p);
    };
    auto xsum = [&](float4 m) -> float4 {
        float lf = __shfl_up_sync(FULLMASK, m.w, 1);
        float rt = __shfl_down_sync(FULLMASK, m.x, 1);
        if (tx == 0)  lf = 0.f;
        if (tx == 31) rt = 0.f;
        float4 r;
        r.x = lf  + m.x + m.y;
        r.y = m.x + m.y + m.z;
        r.z = m.y + m.z + m.w;
        r.w = m.z + m.w + rt;
        return r;
    };

    float4 m0[2], m1[2], m2[2], pm[2];
    #pragma unroll
    for (int j = 0; j < 2; j++) {
        const int k = 2*tk + j;
        m0[j] = ldsq(k, z0 - 1, gy);
        m1[j] = ldsq(k, z0,     gy);
        m2[j] = ldsq(k, z0 + 1, gy);
    }

    float accB[2] = {0,0}, accA[2] = {0,0}, accC[2] = {0,0};
    float4 j2v = make_float4(0.f,0.f,0.f,0.f);

    for (int zi = 0; zi < 16; zi++) {
        const int z = z0 + zi;
        const int slot = z & 1;

        // prefetch z+2 (consumed next iteration)
        #pragma unroll
        for (int j = 0; j < 2; j++) pm[j] = ldsq(2*tk + j, z + 2, gy);

        // halo rows first (L2 latency overlapped by own-row work below)
        float4 h[2];
        const bool eLo = (ty == 0), eHi = (ty == 7);
        if (eLo | eHi) {
            const int hy = eLo ? (y0 - 1) : (y0 + 8);
            #pragma unroll
            for (int j = 0; j < 2; j++) {
                const int k = 2*tk + j;
                h[j] = add4(add4(ldsq(k, z-1, hy), ldsq(k, z, hy)), ldsq(k, z+1, hy));
            }
        }

        // own x-sum-of-z-sum rows
        #pragma unroll
        for (int j = 0; j < 2; j++) {
            const int k = 2*tk + j;
            float4 zs = add4(add4(m0[j], m1[j]), m2[j]);
            s_xs[((slot*4 + k)*10 + ty + 1)*32 + tx] = xsum(zs);
        }
        if (eLo | eHi) {
            const int hr = eLo ? 0 : 9;
            #pragma unroll
            for (int j = 0; j < 2; j++)
                s_xs[((slot*4 + 2*tk + j)*10 + hr)*32 + tx] = xsum(h[j]);
        }
        // center partial M (depends only on m1 -> pre-barrier)
        s_ex[((slot*2 + tk)*8 + ty)*32 + tx] = add4(m1[0], m1[1]);
        __syncthreads();

        const float4 img = *(const float4*)(im_b + (((size_t)z)<<14) + (gy<<7) + (tx<<2));
        float4 s27[2];
        #pragma unroll
        for (int j = 0; j < 2; j++) {
            const float4* base = &s_xs[((slot*4 + 2*tk + j)*10 + ty)*32 + tx];
            s27[j] = add4(add4(base[0], base[32]), base[64]);
        }
        #pragma unroll
        for (int j = 0; j < 2; j++) {
            const float4 mc = m1[j];
            accB[j] += (mc.x + mc.y) + (mc.z + mc.w);
            float tX = mc.x*img.x, tY = mc.y*img.y, tZ = mc.z*img.z, tW = mc.w*img.w;
            accA[j] += (tX + tY) + (tZ + tW);
            accC[j] += fmaf(tX, img.x, fmaf(tY, img.y, fmaf(tZ, img.z, tW*img.w)));
            j2v.x = fmaf(mc.x, mc.x - s27[j].x, j2v.x);
            j2v.y = fmaf(mc.y, mc.y - s27[j].y, j2v.y);
            j2v.z = fmaf(mc.z, mc.z - s27[j].z, j2v.z);
            j2v.w = fmaf(mc.w, mc.w - s27[j].w, j2v.w);
        }
        // cross-k coupling: one group per z-parity computes M*(S-M)
        if (tk == slot) {
            const int ot = tk ^ 1;
            float4 So = make_float4(0.f,0.f,0.f,0.f);
            #pragma unroll
            for (int j = 0; j < 2; j++) {
                const float4* base = &s_xs[((slot*4 + 2*ot + j)*10 + ty)*32 + tx];
                So = add4(So, add4(add4(base[0], base[32]), base[64]));
            }
            float4 S = add4(add4(s27[0], s27[1]), So);
            float4 M = add4(add4(m1[0], m1[1]), s_ex[((slot*2 + ot)*8 + ty)*32 + tx]);
            j2v.x = fmaf(M.x, S.x - M.x, j2v.x);
            j2v.y = fmaf(M.y, S.y - M.y, j2v.y);
            j2v.z = fmaf(M.z, S.z - M.z, j2v.z);
            j2v.w = fmaf(M.w, S.w - M.w, j2v.w);
        }
        #pragma unroll
        for (int j = 0; j < 2; j++) { m0[j] = m1[j]; m1[j] = m2[j]; m2[j] = pm[j]; }
    }

    // ---- reduction ----
    float vals[7] = { accB[0], accB[1], accA[0], accA[1], accC[0], accC[1],
                      (j2v.x + j2v.y) + (j2v.z + j2v.w) };
    #pragma unroll
    for (int q = 0; q < 7; q++) {
        float v = vals[q];
        #pragma unroll
        for (int off = 16; off; off >>= 1) v += __shfl_xor_sync(FULLMASK, v, off);
        vals[q] = v;
    }
    __syncthreads();
    if (tx == 0) {
        #pragma unroll
        for (int q = 0; q < 7; q++) s_red[wid*8 + q] = vals[q];
    }
    __syncthreads();
    if (tid < 14) {
        const int g = tid / 7, q = tid % 7;
        float s = 0.f;
        #pragma unroll
        for (int w = 0; w < 8; w++) s += s_red[(8*g + w)*8 + q];
        double* dst;
        if (q < 2)       dst = &g_acc[b*4 + 2*g + q];
        else if (q < 4)  dst = &g_acc[8 + b*4 + 2*g + (q - 2)];
        else if (q < 6)  dst = &g_acc[16 + b*4 + 2*g + (q - 4)];
        else             dst = &g_acc[24];
        atomicAdd(dst, (double)s);
        __threadfence();
    }
    __syncthreads();

    // ---- last of 256 blocks finalizes + resets for next graph replay ----
    if (tid == 0) {
        unsigned old = atomicAdd(&g_sem, 1u);
        if (old == 255u) {
            volatile double* ga = g_acc;
            double j1 = 0.0;
            #pragma unroll
            for (int i = 0; i < 8; i++) {
                double Bv = ga[i], Av = ga[8 + i], Cv = ga[16 + i];
                j1 += Cv - Av * Av / Bv;
            }
            const double inv = 1.0 / 4194304.0;
            out[0] = (float)(j1 * inv + 0.0008 * ga[24] * inv);
            #pragma unroll
            for (int i = 0; i < 25; i++) g_acc[i] = 0.0;
            g_sem = 0u;
        }
    }
}

extern "C" void kernel_launch(void* const* d_in, const int* in_sizes, int n_in,
                              void* d_out, int out_size) {
    const float* ypred = (const float*)d_in[0];
    const float* image = (const float*)d_in[1];
    if (n_in >= 2 && in_sizes[0] < in_sizes[1]) {  // robustness to input order
        ypred = (const float*)d_in[1];
        image = (const float*)d_in[0];
    }
    cudaFuncSetAttribute(rfcm_kernel, cudaFuncAttributeMaxDynamicSharedMemorySize,
                         SMEM_BYTES);
    rfcm_kernel<<<dim3(16, 8, 2), dim3(32, 8, 2), SMEM_BYTES>>>(ypred, image, (float*)d_out);
}

// round 7
// speedup vs baseline: 1.6982x; 1.6982x over previous
#include <cuda_runtime.h>

// RFCM loss — fused single kernel, v6 (v4 skeleton + 1-barrier parity pipeline).
// y_pred: [2,4,128,128,128] f32, image: [2,1,128,128,128] f32 -> scalar f32.
// J1 = (1/N)*sum_{b,k}(C - A^2/B);  J2 voxel = M*(S27-M) - sum_k mem_k*(s27_k-mem_k)

#define FULLMASK 0xffffffffu

__device__ double g_acc[25];
__device__ unsigned int g_sem;

__device__ __forceinline__ float4 sq4(float4 p) {
    float4 m; m.x=p.x*p.x; m.y=p.y*p.y; m.z=p.z*p.z; m.w=p.w*p.w; return m;
}
__device__ __forceinline__ float4 add4(float4 a, float4 b) {
    float4 r; r.x=a.x+b.x; r.y=a.y+b.y; r.z=a.z+b.z; r.w=a.w+b.w; return r;
}

// dynamic smem: s_xs [slot2][k4][row18][32]f4, s_ex [slot2][grp2][ty16][32]f4, s_red
#define XS_F4 (2*4*18*32)
#define EX_F4 (2*2*16*32)
#define SMEM_BYTES ((XS_F4 + EX_F4)*16 + 32*8*4)

__global__ __launch_bounds__(1024, 1)
void rfcm_kernel(const float* __restrict__ ypred, const float* __restrict__ image,
                 float* __restrict__ out) {
    extern __shared__ float4 smem4[];
    float4* s_xs = smem4;                 // ((slot*4+k)*18+row)*32+tx
    float4* s_ex = smem4 + XS_F4;         // ((slot*2+grp)*16+ty)*32+tx
    float*  s_red = (float*)(smem4 + XS_F4 + EX_F4);

    const int tx = threadIdx.x;           // x quad
    const int ty = threadIdx.y;           // y row 0..15
    const int tk = threadIdx.z;           // k group 0..1
    const int tid = tx + 32*ty + 512*tk;
    const int wid = ty + 16*tk;
    const int y0 = blockIdx.x * 16;
    const int z0 = blockIdx.y * 16;
    const int b  = blockIdx.z;
    const int gy = y0 + ty;
    const bool eLo = (ty == 0), eHi = (ty == 15);
    const int hy = eLo ? (y0 - 1) : (y0 + 16);
    const int hr = eLo ? 0 : 17;

    const float* yp_b = ypred + (size_t)b * 4 * 128 * 16384;
    const float* im_b = image + (size_t)b * 128 * 16384;

    auto ldsq = [&](int k, int zz, int yy) -> float4 {
        float4 p = make_float4(0.f,0.f,0.f,0.f);
        if ((unsigned)zz < 128u && (unsigned)yy < 128u)
            p = *(const float4*)(yp_b + (((size_t)(k*128+zz))<<14) + (yy<<7) + (tx<<2));
        return sq4(p);
    };
    auto xsum = [&](float4 m) -> float4 {
        float lf = __shfl_up_sync(FULLMASK, m.w, 1);
        float rt = __shfl_down_sync(FULLMASK, m.x, 1);
        if (tx == 0)  lf = 0.f;
        if (tx == 31) rt = 0.f;
        float4 r;
        r.x = lf  + m.x + m.y;
        r.y = m.x + m.y + m.z;
        r.z = m.y + m.z + m.w;
        r.w = m.z + m.w + rt;
        return r;
    };

    // rotating raw-mem window: m1=m(z), m2=m(z+1), mn=prefetch m(z+2)
    float4 m1[2], m2[2], mn[2];
    #pragma unroll
    for (int j = 0; j < 2; j++) {
        const int k = 2*tk + j;
        mn[j] = ldsq(k, z0 - 1, gy);   // temporarily m(z0-1) for prologue build
        m1[j] = ldsq(k, z0,     gy);
        m2[j] = ldsq(k, z0 + 1, gy);
    }
    // prologue: build plane z0 into slot (z0&1)
    {
        const int slot = z0 & 1;
        #pragma unroll
        for (int j = 0; j < 2; j++) {
            const int k = 2*tk + j;
            s_xs[((slot*4 + k)*18 + ty + 1)*32 + tx] = xsum(add4(add4(mn[j], m1[j]), m2[j]));
        }
        if (eLo | eHi) {
            #pragma unroll
            for (int j = 0; j < 2; j++) {
                const int k = 2*tk + j;
                float4 zh = add4(add4(ldsq(k, z0-1, hy), ldsq(k, z0, hy)), ldsq(k, z0+1, hy));
                s_xs[((slot*4 + k)*18 + hr)*32 + tx] = xsum(zh);
            }
        }
        s_ex[((slot*2 + tk)*16 + ty)*32 + tx] = add4(m1[0], m1[1]);
    }
    __syncthreads();

    float accB[2] = {0,0}, accA[2] = {0,0}, accC[2] = {0,0};
    float4 j2v = make_float4(0.f,0.f,0.f,0.f);

    for (int zi = 0; zi < 16; zi++) {
        const int z = z0 + zi;
        const int slot = z & 1, nslot = slot ^ 1;
        const bool notlast = (zi != 15);

        // phase 1: issue loads for plane z+1 build (consumed after the consume phase)
        float4 h[2];
        if (notlast) {
            #pragma unroll
            for (int j = 0; j < 2; j++) mn[j] = ldsq(2*tk + j, z + 2, gy);
            if (eLo | eHi) {
                #pragma unroll
                for (int j = 0; j < 2; j++) {
                    const int k = 2*tk + j;
                    h[j] = add4(add4(ldsq(k, z, hy), ldsq(k, z+1, hy)), ldsq(k, z+2, hy));
                }
            }
        }

        // phase 2: consume plane z (math overlaps phase-1 LDGs)
        const float4 img = *(const float4*)(im_b + (((size_t)z)<<14) + (gy<<7) + (tx<<2));
        float4 s27[2];
        #pragma unroll
        for (int j = 0; j < 2; j++) {
            const float4* base = &s_xs[((slot*4 + 2*tk + j)*18 + ty)*32 + tx];
            s27[j] = add4(add4(base[0], base[32]), base[64]);
        }
        #pragma unroll
        for (int j = 0; j < 2; j++) {
            const float4 mc = m1[j];
            accB[j] += (mc.x + mc.y) + (mc.z + mc.w);
            float tX = mc.x*img.x, tY = mc.y*img.y, tZ = mc.z*img.z, tW = mc.w*img.w;
            accA[j] += (tX + tY) + (tZ + tW);
            accC[j] += fmaf(tX, img.x, fmaf(tY, img.y, fmaf(tZ, img.z, tW*img.w)));
            j2v.x = fmaf(mc.x, mc.x - s27[j].x, j2v.x);
            j2v.y = fmaf(mc.y, mc.y - s27[j].y, j2v.y);
            j2v.z = fmaf(mc.z, mc.z - s27[j].z, j2v.z);
            j2v.w = fmaf(mc.w, mc.w - s27[j].w, j2v.w);
        }
        // cross-k coupling: parity-alternating ownership
        if (tk == slot) {
            const int ot = tk ^ 1;
            float4 So = make_float4(0.f,0.f,0.f,0.f);
            #pragma unroll
            for (int j = 0; j < 2; j++) {
                const float4* base = &s_xs[((slot*4 + 2*ot + j)*18 + ty)*32 + tx];
                So = add4(So, add4(add4(base[0], base[32]), base[64]));
            }
            float4 S = add4(add4(s27[0], s27[1]), So);
            float4 M = add4(add4(m1[0], m1[1]), s_ex[((slot*2 + ot)*16 + ty)*32 + tx]);
            j2v.x = fmaf(M.x, S.x - M.x, j2v.x);
            j2v.y = fmaf(M.y, S.y - M.y, j2v.y);
            j2v.z = fmaf(M.z, S.z - M.z, j2v.z);
            j2v.w = fmaf(M.w, S.w - M.w, j2v.w);
        }

        // phase 3: build plane z+1 into nslot, then single barrier
        if (notlast) {
            #pragma unroll
            for (int j = 0; j < 2; j++) {
                const int k = 2*tk + j;
                s_xs[((nslot*4 + k)*18 + ty + 1)*32 + tx] =
                    xsum(add4(add4(m1[j], m2[j]), mn[j]));
            }
            if (eLo | eHi) {
                #pragma unroll
                for (int j = 0; j < 2; j++)
                    s_xs[((nslot*4 + 2*tk + j)*18 + hr)*32 + tx] = xsum(h[j]);
            }
            s_ex[((nslot*2 + tk)*16 + ty)*32 + tx] = add4(m2[0], m2[1]);
            __syncthreads();
            #pragma unroll
            for (int j = 0; j < 2; j++) { m1[j] = m2[j]; m2[j] = mn[j]; }
        }
    }

    // ---- reduction ----
    float vals[7] = { accB[0], accB[1], accA[0], accA[1], accC[0], accC[1],
                      (j2v.x + j2v.y) + (j2v.z + j2v.w) };
    #pragma unroll
    for (int q = 0; q < 7; q++) {
        float v = vals[q];
        #pragma unroll
        for (int off = 16; off; off >>= 1) v += __shfl_xor_sync(FULLMASK, v, off);
        vals[q] = v;
    }
    __syncthreads();
    if (tx == 0) {
        #pragma unroll
        for (int q = 0; q < 7; q++) s_red[wid*8 + q] = vals[q];
    }
    __syncthreads();
    if (tid < 14) {
        const int g = tid / 7, q = tid % 7;
        float s = 0.f;
        #pragma unroll
        for (int w = 0; w < 16; w++) s += s_red[(16*g + w)*8 + q];
        double* dst;
        if (q < 2)       dst = &g_acc[b*4 + 2*g + q];
        else if (q < 4)  dst = &g_acc[8 + b*4 + 2*g + (q - 2)];
        else if (q < 6)  dst = &g_acc[16 + b*4 + 2*g + (q - 4)];
        else             dst = &g_acc[24];
        atomicAdd(dst, (double)s);
        __threadfence();
    }
    __syncthreads();

    // ---- last of 128 blocks finalizes + resets for next graph replay ----
    if (tid == 0) {
        unsigned old = atomicAdd(&g_sem, 1u);
        if (old == 127u) {
            volatile double* ga = g_acc;
            double j1 = 0.0;
            #pragma unroll
            for (int i = 0; i < 8; i++) {
                double Bv = ga[i], Av = ga[8 + i], Cv = ga[16 + i];
                j1 += Cv - Av * Av / Bv;
            }
            const double inv = 1.0 / 4194304.0;
            out[0] = (float)(j1 * inv + 0.0008 * ga[24] * inv);
            #pragma unroll
            for (int i = 0; i < 25; i++) g_acc[i] = 0.0;
            g_sem = 0u;
        }
    }
}

extern "C" void kernel_launch(void* const* d_in, const int* in_sizes, int n_in,
                              void* d_out, int out_size) {
    const float* ypred = (const float*)d_in[0];
    const float* image = (const float*)d_in[1];
    if (n_in >= 2 && in_sizes[0] < in_sizes[1]) {  // robustness to input order
        ypred = (const float*)d_in[1];
        image = (const float*)d_in[0];
    }
    cudaFuncSetAttribute(rfcm_kernel, cudaFuncAttributeMaxDynamicSharedMemorySize,
                         SMEM_BYTES);
    rfcm_kernel<<<dim3(8, 8, 2), dim3(32, 16, 2), SMEM_BYTES>>>(ypred, image, (float*)d_out);
}

// round 8
// speedup vs baseline: 1.9581x; 1.1531x over previous
#include <cuda_runtime.h>

// RFCM loss — fused single kernel, v7 = v4 skeleton + parity double-buffer
// (1 barrier/plane), balanced halo warps, alternating coupling ownership.
// y_pred: [2,4,128,128,128] f32, image: [2,1,128,128,128] f32 -> scalar f32.
// J1 = (1/N)*sum_{b,k}(C - A^2/B);  J2 voxel = M*(S27-M) - sum_k mem_k*(s27_k-mem_k)

#define FULLMASK 0xffffffffu

__device__ double g_acc[25];
__device__ unsigned int g_sem;

__device__ __forceinline__ float4 sq4(float4 p) {
    float4 m; m.x=p.x*p.x; m.y=p.y*p.y; m.z=p.z*p.z; m.w=p.w*p.w; return m;
}
__device__ __forceinline__ float4 add4(float4 a, float4 b) {
    float4 r; r.x=a.x+b.x; r.y=a.y+b.y; r.z=a.z+b.z; r.w=a.w+b.w; return r;
}

// dynamic smem: s_xs [slot2][k4][row18][32]f4, s_ex [slot2][ty16][32]f4, s_red
#define XS_F4 (2*4*18*32)
#define EX_F4 (2*16*32)
#define SMEM_BYTES ((XS_F4 + EX_F4)*16 + 32*8*4)

__global__ __launch_bounds__(1024, 1)
void rfcm_kernel(const float* __restrict__ ypred, const float* __restrict__ image,
                 float* __restrict__ out) {
    extern __shared__ float4 smem4[];
    float4* s_xs = smem4;                 // ((slot*4+k)*18+row)*32+tx
    float4* s_ex = smem4 + XS_F4;         // (slot*16+ty)*32+tx  (non-owner group's M)
    float*  s_red = (float*)(smem4 + XS_F4 + EX_F4);

    const int tx = threadIdx.x;           // x quad
    const int ty = threadIdx.y;           // y row 0..15
    const int tk = threadIdx.z;           // k group 0..1
    const int tid = tx + 32*ty + 512*tk;
    const int wid = ty + 16*tk;
    const int y0 = blockIdx.x * 16;
    const int z0 = blockIdx.y * 8;
    const int b  = blockIdx.z;
    const int gy = y0 + ty;

    // halo task: warps ty<4 of each group own (k = 2tk+(ty&1), side = ty>>1)
    const bool haloW = (ty < 4);
    const int hk = 2*tk + (ty & 1);
    const int hy = (ty >> 1) ? (y0 + 16) : (y0 - 1);
    const int hr = (ty >> 1) ? 17 : 0;

    const float* yp_b = ypred + (size_t)b * 4 * 128 * 16384;
    const float* im_b = image + (size_t)b * 128 * 16384;

    auto ldsq = [&](int k, int zz, int yy) -> float4 {
        float4 p = make_float4(0.f,0.f,0.f,0.f);
        if ((unsigned)zz < 128u && (unsigned)yy < 128u)
            p = *(const float4*)(yp_b + (((size_t)(k*128+zz))<<14) + (yy<<7) + (tx<<2));
        return sq4(p);
    };
    auto xsum = [&](float4 m) -> float4 {
        float lf = __shfl_up_sync(FULLMASK, m.w, 1);
        float rt = __shfl_down_sync(FULLMASK, m.x, 1);
        if (tx == 0)  lf = 0.f;
        if (tx == 31) rt = 0.f;
        float4 r;
        r.x = lf  + m.x + m.y;
        r.y = m.x + m.y + m.z;
        r.z = m.y + m.z + m.w;
        r.w = m.z + m.w + rt;
        return r;
    };

    // rolling raw-mem window (own row, 2 k's): m0=m(z-1), m1=m(z), m2=m(z+1)
    float4 m0[2], m1[2], m2[2];
    #pragma unroll
    for (int j = 0; j < 2; j++) {
        m0[j] = ldsq(2*tk + j, z0 - 1, gy);
        m1[j] = ldsq(2*tk + j, z0,     gy);
    }

    float accB[2] = {0,0}, accA[2] = {0,0}, accC[2] = {0,0};
    float4 j2v = make_float4(0.f,0.f,0.f,0.f);

    for (int zi = 0; zi < 8; zi++) {
        const int z = z0 + zi;
        const int slot = z & 1;

        // -- build plane z into xs[slot] --
        #pragma unroll
        for (int j = 0; j < 2; j++) m2[j] = ldsq(2*tk + j, z + 1, gy);
        const float4 img = *(const float4*)(im_b + (((size_t)z)<<14) + (gy<<7) + (tx<<2));
        if (haloW) {
            float4 zh = add4(add4(ldsq(hk, z-1, hy), ldsq(hk, z, hy)), ldsq(hk, z+1, hy));
            s_xs[((slot*4 + hk)*18 + hr)*32 + tx] = xsum(zh);
        }
        #pragma unroll
        for (int j = 0; j < 2; j++) {
            const int k = 2*tk + j;
            s_xs[((slot*4 + k)*18 + ty + 1)*32 + tx] = xsum(add4(add4(m0[j], m1[j]), m2[j]));
        }
        if (tk != slot)   // non-owner publishes its partial center-M
            s_ex[(slot*16 + ty)*32 + tx] = add4(m1[0], m1[1]);
        __syncthreads();

        // -- consume plane z --
        float4 s27[2];
        #pragma unroll
        for (int j = 0; j < 2; j++) {
            const float4* base = &s_xs[((slot*4 + 2*tk + j)*18 + ty)*32 + tx];
            s27[j] = add4(add4(base[0], base[32]), base[64]);
        }
        #pragma unroll
        for (int j = 0; j < 2; j++) {
            const float4 mc = m1[j];
            accB[j] += (mc.x + mc.y) + (mc.z + mc.w);
            float tX = mc.x*img.x, tY = mc.y*img.y, tZ = mc.z*img.z, tW = mc.w*img.w;
            accA[j] += (tX + tY) + (tZ + tW);
            accC[j] += fmaf(tX, img.x, fmaf(tY, img.y, fmaf(tZ, img.z, tW*img.w)));
            j2v.x = fmaf(mc.x, mc.x - s27[j].x, j2v.x);
            j2v.y = fmaf(mc.y, mc.y - s27[j].y, j2v.y);
            j2v.z = fmaf(mc.z, mc.z - s27[j].z, j2v.z);
            j2v.w = fmaf(mc.w, mc.w - s27[j].w, j2v.w);
        }
        if (tk == slot) {  // coupling owner this parity
            const int ot = tk ^ 1;
            float4 So = make_float4(0.f,0.f,0.f,0.f);
            #pragma unroll
            for (int j = 0; j < 2; j++) {
                const float4* base = &s_xs[((slot*4 + 2*ot + j)*18 + ty)*32 + tx];
                So = add4(So, add4(add4(base[0], base[32]), base[64]));
            }
            float4 S = add4(add4(s27[0], s27[1]), So);
            float4 M = add4(add4(m1[0], m1[1]), s_ex[(slot*16 + ty)*32 + tx]);
            j2v.x = fmaf(M.x, S.x - M.x, j2v.x);
            j2v.y = fmaf(M.y, S.y - M.y, j2v.y);
            j2v.z = fmaf(M.z, S.z - M.z, j2v.z);
            j2v.w = fmaf(M.w, S.w - M.w, j2v.w);
        }
        #pragma unroll
        for (int j = 0; j < 2; j++) { m0[j] = m1[j]; m1[j] = m2[j]; }
    }

    // ---- reduction ----
    float vals[7] = { accB[0], accB[1], accA[0], accA[1], accC[0], accC[1],
                      (j2v.x + j2v.y) + (j2v.z + j2v.w) };
    #pragma unroll
    for (int q = 0; q < 7; q++) {
        float v = vals[q];
        #pragma unroll
        for (int off = 16; off; off >>= 1) v += __shfl_xor_sync(FULLMASK, v, off);
        vals[q] = v;
    }
    __syncthreads();
    if (tx == 0) {
        #pragma unroll
        for (int q = 0; q < 7; q++) s_red[wid*8 + q] = vals[q];
    }
    __syncthreads();
    if (tid < 14) {
        const int g = tid / 7, q = tid % 7;
        float s = 0.f;
        #pragma unroll
        for (int w = 0; w < 16; w++) s += s_red[(16*g + w)*8 + q];
        double* dst;
        if (q < 2)       dst = &g_acc[b*4 + 2*g + q];
        else if (q < 4)  dst = &g_acc[8 + b*4 + 2*g + (q - 2)];
        else if (q < 6)  dst = &g_acc[16 + b*4 + 2*g + (q - 4)];
        else             dst = &g_acc[24];
        atomicAdd(dst, (double)s);
        __threadfence();
    }
    __syncthreads();

    // ---- last of 256 blocks finalizes + resets for next graph replay ----
    if (tid == 0) {
        unsigned old = atomicAdd(&g_sem, 1u);
        if (old == 255u) {
            volatile double* ga = g_acc;
            double j1 = 0.0;
            #pragma unroll
            for (int i = 0; i < 8; i++) {
                double Bv = ga[i], Av = ga[8 + i], Cv = ga[16 + i];
                j1 += Cv - Av * Av / Bv;
            }
            const double inv = 1.0 / 4194304.0;
            out[0] = (float)(j1 * inv + 0.0008 * ga[24] * inv);
            #pragma unroll
            for (int i = 0; i < 25; i++) g_acc[i] = 0.0;
            g_sem = 0u;
        }
    }
}

extern "C" void kernel_launch(void* const* d_in, const int* in_sizes, int n_in,
                              void* d_out, int out_size) {
    const float* ypred = (const float*)d_in[0];
    const float* image = (const float*)d_in[1];
    if (n_in >= 2 && in_sizes[0] < in_sizes[1]) {  // robustness to input order
        ypred = (const float*)d_in[1];
        image = (const float*)d_in[0];
    }
    cudaFuncSetAttribute(rfcm_kernel, cudaFuncAttributeMaxDynamicSharedMemorySize,
                         SMEM_BYTES);
    rfcm_kernel<<<dim3(8, 16, 2), dim3(32, 16, 2), SMEM_BYTES>>>(ypred, image, (float*)d_out);
}

// round 9
// speedup vs baseline: 2.0926x; 1.0687x over previous
#include <cuda_runtime.h>

// RFCM loss — fused single kernel, v8: adjoint-factored J2.
// J1 = (1/N)*sum_{b,k}(C - A^2/B); A=sum(mem*img), B=sum(mem), C=sum(mem*img^2)
// J2 = 2*sum_{k<k'} [ <Bx(mem_k), ByBz(mem_k')> - <mem_k, mem_k'> ]   (self-terms cancel)
// mem = y_pred^2, zero-padded 3x3x3 box stencil.

#define FULLMASK 0xffffffffu

__device__ double g_acc[25];
__device__ unsigned int g_sem;

__device__ __forceinline__ float4 sq4(float4 p) {
    float4 m; m.x=p.x*p.x; m.y=p.y*p.y; m.z=p.z*p.z; m.w=p.w*p.w; return m;
}
__device__ __forceinline__ float4 add4(float4 a, float4 b) {
    float4 r; r.x=a.x+b.x; r.y=a.y+b.y; r.z=a.z+b.z; r.w=a.w+b.w; return r;
}

// dynamic smem: s_zs [slot2][k4][row18][32]f4 (raw z-sums), s_ex [slot2][ty16][32]f4, s_red
#define ZS_F4 (2*4*18*32)
#define EX_F4 (2*16*32)
#define SMEM_BYTES ((ZS_F4 + EX_F4)*16 + 32*8*4)

__global__ __launch_bounds__(1024, 1)
void rfcm_kernel(const float* __restrict__ ypred, const float* __restrict__ image,
                 float* __restrict__ out) {
    extern __shared__ float4 smem4[];
    float4* s_zs = smem4;                 // ((slot*4+k)*18+row)*32+tx
    float4* s_ex = smem4 + ZS_F4;         // (slot*16+ty)*32+tx : non-owner center sum
    float*  s_red = (float*)(smem4 + ZS_F4 + EX_F4);

    const int tx = threadIdx.x;           // x quad
    const int ty = threadIdx.y;           // y row 0..15
    const int tk = threadIdx.z;           // k group 0..1 (k = 2tk, 2tk+1)
    const int tid = tx + 32*ty + 512*tk;
    const int wid = ty + 16*tk;
    const int y0 = blockIdx.x * 16;
    const int z0 = blockIdx.y * 8;
    const int b  = blockIdx.z;
    const int gy = y0 + ty;

    // halo: 8 tasks (4k x 2 sides) on warps ty<4 of each group
    const bool haloW = (ty < 4);
    const int hk = 2*tk + (ty & 1);
    const int hy = (ty >> 1) ? (y0 + 16) : (y0 - 1);
    const int hr = (ty >> 1) ? 17 : 0;

    const float* yp_b = ypred + (size_t)b * 4 * 128 * 16384;
    const float* im_b = image + (size_t)b * 128 * 16384;

    auto ldsq = [&](int k, int zz, int yy) -> float4 {
        float4 p = make_float4(0.f,0.f,0.f,0.f);
        if ((unsigned)zz < 128u && (unsigned)yy < 128u)
            p = *(const float4*)(yp_b + (((size_t)(k*128+zz))<<14) + (yy<<7) + (tx<<2));
        return sq4(p);
    };
    auto xsum = [&](float4 m) -> float4 {     // Bx via shuffles (zero-pad x edges)
        float lf = __shfl_up_sync(FULLMASK, m.w, 1);
        float rt = __shfl_down_sync(FULLMASK, m.x, 1);
        if (tx == 0)  lf = 0.f;
        if (tx == 31) rt = 0.f;
        float4 r;
        r.x = lf  + m.x + m.y;
        r.y = m.x + m.y + m.z;
        r.z = m.y + m.z + m.w;
        r.w = m.z + m.w + rt;
        return r;
    };

    // rolling raw-mem window: m0=m(z-1), m1=m(z), m2=m(z+1), per group's 2 k's
    float4 m0[2], m1[2], m2[2];
    #pragma unroll
    for (int j = 0; j < 2; j++) {
        m0[j] = ldsq(2*tk + j, z0 - 1, gy);
        m1[j] = ldsq(2*tk + j, z0,     gy);
    }

    float accB[2] = {0,0}, accA[2] = {0,0}, accC[2] = {0,0};
    float4 j2v = make_float4(0.f,0.f,0.f,0.f);

    for (int zi = 0; zi < 8; zi++) {
        const int z = z0 + zi;
        const int slot = z & 1;

        // ---- build: z-sums to smem ----
        #pragma unroll
        for (int j = 0; j < 2; j++) m2[j] = ldsq(2*tk + j, z + 1, gy);
        const float4 img = *(const float4*)(im_b + (((size_t)z)<<14) + (gy<<7) + (tx<<2));
        float4 zs[2];
        #pragma unroll
        for (int j = 0; j < 2; j++) {
            zs[j] = add4(add4(m0[j], m1[j]), m2[j]);
            s_zs[((slot*4 + 2*tk + j)*18 + ty + 1)*32 + tx] = zs[j];
        }
        if (haloW) {
            float4 zh = add4(add4(ldsq(hk, z-1, hy), ldsq(hk, z, hy)), ldsq(hk, z+1, hy));
            s_zs[((slot*4 + hk)*18 + hr)*32 + tx] = zh;
        }
        if (tk != slot)   // non-owner publishes its center partial sum
            s_ex[(slot*16 + ty)*32 + tx] = add4(m1[0], m1[1]);
        __syncthreads();

        // ---- consume ----
        // J1 terms
        #pragma unroll
        for (int j = 0; j < 2; j++) {
            const float4 mc = m1[j];
            accB[j] += (mc.x + mc.y) + (mc.z + mc.w);
            float tX = mc.x*img.x, tY = mc.y*img.y, tZ = mc.z*img.z, tW = mc.w*img.w;
            accA[j] += (tX + tY) + (tZ + tW);
            accC[j] += fmaf(tX, img.x, fmaf(tY, img.y, fmaf(tZ, img.z, tW*img.w)));
        }
        // local pair (2tk, 2tk+1): <a0, b1> - <m0, m1>
        const float4 a0 = xsum(m1[0]);
        {
            const float4* zb = &s_zs[((slot*4 + 2*tk + 1)*18 + ty)*32 + tx];
            float4 b1 = add4(add4(zb[0], zs[1]), zb[64]);   // rows ty, ty+1(own), ty+2
            j2v.x += fmaf(a0.x, b1.x, -m1[0].x * m1[1].x);
            j2v.y += fmaf(a0.y, b1.y, -m1[0].y * m1[1].y);
            j2v.z += fmaf(a0.z, b1.z, -m1[0].z * m1[1].z);
            j2v.w += fmaf(a0.w, b1.w, -m1[0].w * m1[1].w);
        }
        // cross pairs (group A x group B), owner alternates by parity:
        // <a0+a1, bO0+bO1> - <m1[0]+m1[1], otherCenter>
        if (tk == slot) {
            const int ko = 2*(tk ^ 1);
            const float4* z0p = &s_zs[((slot*4 + ko)*18 + ty)*32 + tx];
            const float4* z1p = &s_zs[((slot*4 + ko + 1)*18 + ty)*32 + tx];
            float4 bO = add4(add4(add4(z0p[0], z1p[0]), add4(z0p[32], z1p[32])),
                             add4(z0p[64], z1p[64]));
            float4 aS = add4(a0, xsum(m1[1]));
            float4 cS = add4(m1[0], m1[1]);
            float4 cO = s_ex[(slot*16 + ty)*32 + tx];
            j2v.x += fmaf(aS.x, bO.x, -cS.x * cO.x);
            j2v.y += fmaf(aS.y, bO.y, -cS.y * cO.y);
            j2v.z += fmaf(aS.z, bO.z, -cS.z * cO.z);
            j2v.w += fmaf(aS.w, bO.w, -cS.w * cO.w);
        }
        #pragma unroll
        for (int j = 0; j < 2; j++) { m0[j] = m1[j]; m1[j] = m2[j]; }
    }

    // ---- reduction (J2 gets the symmetry factor 2) ----
    float vals[7] = { accB[0], accB[1], accA[0], accA[1], accC[0], accC[1],
                      2.f * ((j2v.x + j2v.y) + (j2v.z + j2v.w)) };
    #pragma unroll
    for (int q = 0; q < 7; q++) {
        float v = vals[q];
        #pragma unroll
        for (int off = 16; off; off >>= 1) v += __shfl_xor_sync(FULLMASK, v, off);
        vals[q] = v;
    }
    __syncthreads();
    if (tx == 0) {
        #pragma unroll
        for (int q = 0; q < 7; q++) s_red[wid*8 + q] = vals[q];
    }
    __syncthreads();
    if (tid < 14) {
        const int g = tid / 7, q = tid % 7;
        float s = 0.f;
        #pragma unroll
        for (int w = 0; w < 16; w++) s += s_red[(16*g + w)*8 + q];
        double* dst;
        if (q < 2)       dst = &g_acc[b*4 + 2*g + q];
        else if (q < 4)  dst = &g_acc[8 + b*4 + 2*g + (q - 2)];
        else if (q < 6)  dst = &g_acc[16 + b*4 + 2*g + (q - 4)];
        else             dst = &g_acc[24];
        atomicAdd(dst, (double)s);
        __threadfence();
    }
    __syncthreads();

    // ---- last of 256 blocks finalizes + resets for next graph replay ----
    if (tid == 0) {
        unsigned old = atomicAdd(&g_sem, 1u);
        if (old == 255u) {
            volatile double* ga = g_acc;
            double j1 = 0.0;
            #pragma unroll
            for (int i = 0; i < 8; i++) {
                double Bv = ga[i], Av = ga[8 + i], Cv = ga[16 + i];
                j1 += Cv - Av * Av / Bv;
            }
            const double inv = 1.0 / 4194304.0;
            out[0] = (float)(j1 * inv + 0.0008 * ga[24] * inv);
            #pragma unroll
            for (int i = 0; i < 25; i++) g_acc[i] = 0.0;
            g_sem = 0u;
        }
    }
}

extern "C" void kernel_launch(void* const* d_in, const int* in_sizes, int n_in,
                              void* d_out, int out_size) {
    const float* ypred = (const float*)d_in[0];
    const float* image = (const float*)d_in[1];
    if (n_in >= 2 && in_sizes[0] < in_sizes[1]) {  // robustness to input order
        ypred = (const float*)d_in[1];
        image = (const float*)d_in[0];
    }
    cudaFuncSetAttribute(rfcm_kernel, cudaFuncAttributeMaxDynamicSharedMemorySize,
                         SMEM_BYTES);
    rfcm_kernel<<<dim3(8, 16, 2), dim3(32, 16, 2), SMEM_BYTES>>>(ypred, image, (float*)d_out);
}

// round 10
// speedup vs baseline: 2.2193x; 1.0606x over previous
#include <cuda_runtime.h>

// RFCM loss — fused single kernel, v9: adjoint J2 + 512-thr / 2-blocks-per-SM
// single-wave shape, hoisted halo loads.
// J1 = (1/N)*sum_{b,k}(C - A^2/B); A=sum(mem*img), B=sum(mem), C=sum(mem*img^2)
// J2 = 2*sum_{k<k'} [ <Bx(mem_k), ByBz(mem_k')> - <mem_k, mem_k'> ]
// mem = y_pred^2, zero-padded 3x3x3 box stencil.

#define FULLMASK 0xffffffffu

__device__ double g_acc[25];
__device__ unsigned int g_sem;

__device__ __forceinline__ float4 sq4(float4 p) {
    float4 m; m.x=p.x*p.x; m.y=p.y*p.y; m.z=p.z*p.z; m.w=p.w*p.w; return m;
}
__device__ __forceinline__ float4 add4(float4 a, float4 b) {
    float4 r; r.x=a.x+b.x; r.y=a.y+b.y; r.z=a.z+b.z; r.w=a.w+b.w; return r;
}

// smem: s_zs [slot2][k4][row10][32]f4, s_ex [slot2][ty8][32]f4, s_red 16*8 floats
#define ZS_F4 (2*4*10*32)
#define EX_F4 (2*8*32)
#define SMEM_BYTES ((ZS_F4 + EX_F4)*16 + 16*8*4)

__global__ __launch_bounds__(512, 2)
void rfcm_kernel(const float* __restrict__ ypred, const float* __restrict__ image,
                 float* __restrict__ out) {
    extern __shared__ float4 smem4[];
    float4* s_zs = smem4;                 // ((slot*4+k)*10+row)*32+tx
    float4* s_ex = smem4 + ZS_F4;         // (slot*8+ty)*32+tx : non-owner center sum
    float*  s_red = (float*)(smem4 + ZS_F4 + EX_F4);

    const int tx = threadIdx.x;           // x quad
    const int ty = threadIdx.y;           // y row 0..7
    const int tk = threadIdx.z;           // k group 0..1 (k = 2tk, 2tk+1)
    const int tid = tx + 32*ty + 256*tk;
    const int wid = ty + 8*tk;
    const int y0 = blockIdx.x * 8;
    const int z0 = blockIdx.y * 16;
    const int b  = blockIdx.z;
    const int gy = y0 + ty;

    // halo: 8 tasks (4k x 2 sides) on warps ty<4 of each group
    const bool haloW = (ty < 4);
    const int hk = 2*tk + (ty & 1);
    const int hy = (ty >> 1) ? (y0 + 8) : (y0 - 1);
    const int hr = (ty >> 1) ? 9 : 0;

    const float* yp_b = ypred + (size_t)b * 4 * 128 * 16384;
    const float* im_b = image + (size_t)b * 128 * 16384;

    auto ldsq = [&](int k, int zz, int yy) -> float4 {
        float4 p = make_float4(0.f,0.f,0.f,0.f);
        if ((unsigned)zz < 128u && (unsigned)yy < 128u)
            p = *(const float4*)(yp_b + (((size_t)(k*128+zz))<<14) + (yy<<7) + (tx<<2));
        return sq4(p);
    };
    auto xsum = [&](float4 m) -> float4 {     // Bx via shuffles, zero-pad x edges
        float lf = __shfl_up_sync(FULLMASK, m.w, 1);
        float rt = __shfl_down_sync(FULLMASK, m.x, 1);
        if (tx == 0)  lf = 0.f;
        if (tx == 31) rt = 0.f;
        float4 r;
        r.x = lf  + m.x + m.y;
        r.y = m.x + m.y + m.z;
        r.z = m.y + m.z + m.w;
        r.w = m.z + m.w + rt;
        return r;
    };

    // rolling raw-mem window: m0=m(z-1), m1=m(z), m2=m(z+1), per group's 2 k's
    float4 m0[2], m1[2], m2[2];
    #pragma unroll
    for (int j = 0; j < 2; j++) {
        m0[j] = ldsq(2*tk + j, z0 - 1, gy);
        m1[j] = ldsq(2*tk + j, z0,     gy);
    }

    float accB[2] = {0,0}, accA[2] = {0,0}, accC[2] = {0,0};
    float j2 = 0.f;

    for (int zi = 0; zi < 16; zi++) {
        const int z = z0 + zi;
        const int slot = z & 1;

        // ---- issue halo loads FIRST (latency overlapped by own-row work) ----
        float4 hA, hB, hC;
        if (haloW) {
            hA = ldsq(hk, z-1, hy);
            hB = ldsq(hk, z,   hy);
            hC = ldsq(hk, z+1, hy);
        }
        // own z+1 plane + image
        #pragma unroll
        for (int j = 0; j < 2; j++) m2[j] = ldsq(2*tk + j, z + 1, gy);
        const float4 img = *(const float4*)(im_b + (((size_t)z)<<14) + (gy<<7) + (tx<<2));

        // ---- build: z-sums to smem ----
        float4 zs[2];
        #pragma unroll
        for (int j = 0; j < 2; j++) {
            zs[j] = add4(add4(m0[j], m1[j]), m2[j]);
            s_zs[((slot*4 + 2*tk + j)*10 + ty + 1)*32 + tx] = zs[j];
        }
        if (haloW)
            s_zs[((slot*4 + hk)*10 + hr)*32 + tx] = add4(add4(hA, hB), hC);
        if (tk != slot)   // non-owner publishes its center partial sum
            s_ex[(slot*8 + ty)*32 + tx] = add4(m1[0], m1[1]);
        __syncthreads();

        // ---- consume plane z ----
        float4 jv = make_float4(0.f,0.f,0.f,0.f);
        #pragma unroll
        for (int j = 0; j < 2; j++) {
            const float4 mc = m1[j];
            accB[j] += (mc.x + mc.y) + (mc.z + mc.w);
            float tX = mc.x*img.x, tY = mc.y*img.y, tZ = mc.z*img.z, tW = mc.w*img.w;
            accA[j] += (tX + tY) + (tZ + tW);
            accC[j] += fmaf(tX, img.x, fmaf(tY, img.y, fmaf(tZ, img.z, tW*img.w)));
        }
        // local pair (2tk, 2tk+1): <Bx m0, ByBz m1> - <m0, m1>
        const float4 a0 = xsum(m1[0]);
        {
            const float4* zb = &s_zs[((slot*4 + 2*tk + 1)*10 + ty)*32 + tx];
            float4 b1 = add4(add4(zb[0], zs[1]), zb[64]);
            jv.x = fmaf(a0.x, b1.x, -m1[0].x * m1[1].x);
            jv.y = fmaf(a0.y, b1.y, -m1[0].y * m1[1].y);
            jv.z = fmaf(a0.z, b1.z, -m1[0].z * m1[1].z);
            jv.w = fmaf(a0.w, b1.w, -m1[0].w * m1[1].w);
        }
        // cross pairs (group x group), owner alternates by z-parity
        if (tk == slot) {
            const int ko = 2*(tk ^ 1);
            const float4* z0p = &s_zs[((slot*4 + ko)*10 + ty)*32 + tx];
            const float4* z1p = &s_zs[((slot*4 + ko + 1)*10 + ty)*32 + tx];
            float4 bO = add4(add4(add4(z0p[0], z1p[0]), add4(z0p[32], z1p[32])),
                             add4(z0p[64], z1p[64]));
            float4 aS = add4(a0, xsum(m1[1]));
            float4 cS = add4(m1[0], m1[1]);
            float4 cO = s_ex[(slot*8 + ty)*32 + tx];
            jv.x = fmaf(aS.x, bO.x, fmaf(-cS.x, cO.x, jv.x));
            jv.y = fmaf(aS.y, bO.y, fmaf(-cS.y, cO.y, jv.y));
            jv.z = fmaf(aS.z, bO.z, fmaf(-cS.z, cO.z, jv.z));
            jv.w = fmaf(aS.w, bO.w, fmaf(-cS.w, cO.w, jv.w));
        }
        j2 += (jv.x + jv.y) + (jv.z + jv.w);

        #pragma unroll
        for (int j = 0; j < 2; j++) { m0[j] = m1[j]; m1[j] = m2[j]; }
    }

    // ---- reduction (J2 carries symmetry factor 2) ----
    float vals[7] = { accB[0], accB[1], accA[0], accA[1], accC[0], accC[1], 2.f * j2 };
    #pragma unroll
    for (int q = 0; q < 7; q++) {
        float v = vals[q];
        #pragma unroll
        for (int off = 16; off; off >>= 1) v += __shfl_xor_sync(FULLMASK, v, off);
        vals[q] = v;
    }
    __syncthreads();
    if (tx == 0) {
        #pragma unroll
        for (int q = 0; q < 7; q++) s_red[wid*8 + q] = vals[q];
    }
    __syncthreads();
    if (tid < 14) {
        const int g = tid / 7, q = tid % 7;
        float s = 0.f;
        #pragma unroll
        for (int w = 0; w < 8; w++) s += s_red[(8*g + w)*8 + q];
        double* dst;
        if (q < 2)       dst = &g_acc[b*4 + 2*g + q];
        else if (q < 4)  dst = &g_acc[8 + b*4 + 2*g + (q - 2)];
        else if (q < 6)  dst = &g_acc[16 + b*4 + 2*g + (q - 4)];
        else             dst = &g_acc[24];
        atomicAdd(dst, (double)s);
        __threadfence();
    }
    __syncthreads();

    // ---- last of 256 blocks finalizes + resets for next graph replay ----
    if (tid == 0) {
        unsigned old = atomicAdd(&g_sem, 1u);
        if (old == 255u) {
            volatile double* ga = g_acc;
            double j1 = 0.0;
            #pragma unroll
            for (int i = 0; i < 8; i++) {
                double Bv = ga[i], Av = ga[8 + i], Cv = ga[16 + i];
                j1 += Cv - Av * Av / Bv;
            }
            const double inv = 1.0 / 4194304.0;
            out[0] = (float)(j1 * inv + 0.0008 * ga[24] * inv);
            #pragma unroll
            for (int i = 0; i < 25; i++) g_acc[i] = 0.0;
            g_sem = 0u;
        }
    }
}

extern "C" void kernel_launch(void* const* d_in, const int* in_sizes, int n_in,
                              void* d_out, int out_size) {
    const float* ypred = (const float*)d_in[0];
    const float* image = (const float*)d_in[1];
    if (n_in >= 2 && in_sizes[0] < in_sizes[1]) {  // robustness to input order
        ypred = (const float*)d_in[1];
        image = (const float*)d_in[0];
    }
    cudaFuncSetAttribute(rfcm_kernel, cudaFuncAttributeMaxDynamicSharedMemorySize,
                         SMEM_BYTES);
    rfcm_kernel<<<dim3(16, 8, 2), dim3(32, 8, 2), SMEM_BYTES>>>(ypred, image, (float*)d_out);
}

// round 11
// speedup vs baseline: 2.4388x; 1.0989x over previous
#include <cuda_runtime.h>

// RFCM loss — fused single kernel, v10: v9 + pointer-increment addressing
// + halo raw-ring (1 halo LDG/plane).
// J1 = (1/N)*sum_{b,k}(C - A^2/B); A=sum(mem*img), B=sum(mem), C=sum(mem*img^2)
// J2 = 2*sum_{k<k'} [ <Bx(mem_k), ByBz(mem_k')> - <mem_k, mem_k'> ]
// mem = y_pred^2, zero-padded 3x3x3 box stencil.

#define FULLMASK 0xffffffffu

__device__ double g_acc[25];
__device__ unsigned int g_sem;

__device__ __forceinline__ float4 sq4(float4 p) {
    float4 m; m.x=p.x*p.x; m.y=p.y*p.y; m.z=p.z*p.z; m.w=p.w*p.w; return m;
}
__device__ __forceinline__ float4 add4(float4 a, float4 b) {
    float4 r; r.x=a.x+b.x; r.y=a.y+b.y; r.z=a.z+b.z; r.w=a.w+b.w; return r;
}

// smem (float4): s_zs [slot2][k4][row10][32], s_ex [slot2][ty8][32], s_hr [3][8][32], s_red
#define ZS_F4 (2*4*10*32)
#define EX_F4 (2*8*32)
#define HR_F4 (3*8*32)
#define SLOT_F4 (4*10*32)     // 1280
#define SMEM_BYTES ((ZS_F4 + EX_F4 + HR_F4)*16 + 16*8*4)

__global__ __launch_bounds__(512, 2)
void rfcm_kernel(const float* __restrict__ ypred, const float* __restrict__ image,
                 float* __restrict__ out) {
    extern __shared__ float4 smem4[];
    float4* s_zs = smem4;                       // ((slot*4+k)*10+row)*32+tx
    float4* s_ex = smem4 + ZS_F4;               // (slot*8+ty)*32+tx
    float4* s_hr = smem4 + ZS_F4 + EX_F4;       // (hslot*8+hid)*32+tx
    float*  s_red = (float*)(smem4 + ZS_F4 + EX_F4 + HR_F4);

    const int tx = threadIdx.x;
    const int ty = threadIdx.y;                 // y row 0..7
    const int tk = threadIdx.z;                 // k group: ks = 2tk, 2tk+1
    const int tid = tx + 32*ty + 256*tk;
    const int wid = ty + 8*tk;
    const int y0 = blockIdx.x * 8;
    const int z0 = blockIdx.y * 16;
    const int b  = blockIdx.z;
    const int gy = y0 + ty;
    const int ks = 2*tk;

    // halo tasks: warps ty<4 per group own (hk = 2tk+(ty&1), side = ty>>1)
    const bool haloW = (ty < 4);
    const int hk = ks + (ty & 1);
    const int hy = (ty >> 1) ? (y0 + 8) : (y0 - 1);
    const int hr = (ty >> 1) ? 9 : 0;
    const int hid = tk*4 + ty;                  // 0..7 unique per halo task
    const bool hyOK = (unsigned)hy < 128u;

    const float* yp_b = ypred + (size_t)b * 4 * 128 * 16384;
    const float* im_b = image + (size_t)b * 128 * 16384;

    auto ldsq = [&](int k, int zz, int yy) -> float4 {   // prologue-only path
        float4 p = make_float4(0.f,0.f,0.f,0.f);
        if ((unsigned)zz < 128u && (unsigned)yy < 128u)
            p = *(const float4*)(yp_b + (((size_t)(k*128+zz))<<14) + (yy<<7) + (tx<<2));
        return sq4(p);
    };
    auto xsum = [&](float4 m) -> float4 {
        float lf = __shfl_up_sync(FULLMASK, m.w, 1);
        float rt = __shfl_down_sync(FULLMASK, m.x, 1);
        if (tx == 0)  lf = 0.f;
        if (tx == 31) rt = 0.f;
        float4 r;
        r.x = lf  + m.x + m.y;
        r.y = m.x + m.y + m.z;
        r.z = m.y + m.z + m.w;
        r.w = m.z + m.w + rt;
        return r;
    };

    // ---- streaming pointers (advance by one z-plane = 4096 float4 per iter) ----
    const float4* pOwn0 = (const float4*)(yp_b + (((size_t)(ks*128 + z0 + 1))<<14) + (gy<<7) + (tx<<2));
    const float4* pOwn1 = (const float4*)(yp_b + (((size_t)((ks+1)*128 + z0 + 1))<<14) + (gy<<7) + (tx<<2));
    const float4* pImg  = (const float4*)(im_b + (((size_t)z0)<<14) + (gy<<7) + (tx<<2));
    const float4* pHal  = (const float4*)(yp_b + (((size_t)(hk*128 + z0 + 1))<<14) + ((hy & 127)<<7) + (tx<<2));

    // smem base pointers (slot 0); per-parity offset = slot*SLOT_F4
    float4* zOwnS0 = &s_zs[((ks    )*10 + ty + 1)*32 + tx];
    float4* zOwnS1 = &s_zs[((ks + 1)*10 + ty + 1)*32 + tx];
    float4* zHalS  = &s_zs[(hk*10 + hr)*32 + tx];
    const float4* zLoc  = &s_zs[((ks + 1)*10 + ty)*32 + tx];      // local-pair By base
    const int ko = 2*(tk ^ 1);
    const float4* zOth0 = &s_zs[((ko    )*10 + ty)*32 + tx];
    const float4* zOth1 = &s_zs[((ko + 1)*10 + ty)*32 + tx];
    float4* exMine = &s_ex[ty*32 + tx];                            // + slot*256
    float4* hRing  = &s_hr[hid*32 + tx];                           // + hslot*256

    // rolling raw window m0=m(z-1), m1=m(z)
    float4 m0[2], m1[2], m2[2];
    m0[0] = ldsq(ks,   z0 - 1, gy);
    m0[1] = ldsq(ks+1, z0 - 1, gy);
    m1[0] = ldsq(ks,   z0,     gy);
    m1[1] = ldsq(ks+1, z0,     gy);
    // prologue halo ring: slots for zz=z0-1 -> (z0)%3, zz=z0 -> (z0+1)%3
    if (haloW) {
        hRing[((z0    ) % 3) * 256] = ldsq(hk, z0 - 1, hy);
        hRing[((z0 + 1) % 3) * 256] = ldsq(hk, z0,     hy);
    }

    float accB[2] = {0,0}, accA[2] = {0,0}, accC[2] = {0,0};
    float j2 = 0.f;

    for (int zi = 0; zi < 16; zi++) {
        const int z = z0 + zi;
        const int slot = z & 1;
        const int so = slot * SLOT_F4;
        const bool zOK = (z + 1 < 128);

        // ---- loads (issued first, latency covered by build+consume math) ----
        float4 hv = make_float4(0.f,0.f,0.f,0.f);
        if (haloW) { if (zOK & hyOK) hv = sq4(*pHal); pHal += 4096; }
        m2[0] = zOK ? sq4(*pOwn0) : make_float4(0.f,0.f,0.f,0.f);
        m2[1] = zOK ? sq4(*pOwn1) : make_float4(0.f,0.f,0.f,0.f);
        pOwn0 += 4096; pOwn1 += 4096;
        const float4 img = *pImg; pImg += 4096;

        // ---- build plane z ----
        float4 zs1;
        zOwnS0[so] = add4(add4(m0[0], m1[0]), m2[0]);
        zs1 = add4(add4(m0[1], m1[1]), m2[1]);
        zOwnS1[so] = zs1;
        if (haloW) {
            hRing[((z + 2) % 3) * 256] = hv;  // raw ring slot for plane z+1
            // z-sum = sum of all 3 ring slots (contain z-1, z, z+1 in some order)
            zHalS[so] = add4(add4(hRing[0], hRing[256]), hRing[512]);
        }
        if (tk != slot)
            exMine[slot * 256] = add4(m1[0], m1[1]);
        __syncthreads();

        // ---- consume plane z ----
        float4 jv;
        #pragma unroll
        for (int j = 0; j < 2; j++) {
            const float4 mc = m1[j];
            accB[j] += (mc.x + mc.y) + (mc.z + mc.w);
            float tX = mc.x*img.x, tY = mc.y*img.y, tZ = mc.z*img.z, tW = mc.w*img.w;
            accA[j] += (tX + tY) + (tZ + tW);
            accC[j] += fmaf(tX, img.x, fmaf(tY, img.y, fmaf(tZ, img.z, tW*img.w)));
        }
        const float4 a0 = xsum(m1[0]);
        {
            float4 b1 = add4(add4(zLoc[so], zs1), zLoc[so + 64]);
            jv.x = fmaf(a0.x, b1.x, -m1[0].x * m1[1].x);
            jv.y = fmaf(a0.y, b1.y, -m1[0].y * m1[1].y);
            jv.z = fmaf(a0.z, b1.z, -m1[0].z * m1[1].z);
            jv.w = fmaf(a0.w, b1.w, -m1[0].w * m1[1].w);
        }
        if (tk == slot) {
            float4 bO = add4(add4(add4(zOth0[so], zOth1[so]),
                                  add4(zOth0[so + 32], zOth1[so + 32])),
                             add4(zOth0[so + 64], zOth1[so + 64]));
            float4 aS = add4(a0, xsum(m1[1]));
            float4 cS = add4(m1[0], m1[1]);
            float4 cO = s_ex[slot*256 + ty*32 + tx];
            jv.x = fmaf(aS.x, bO.x, fmaf(-cS.x, cO.x, jv.x));
            jv.y = fmaf(aS.y, bO.y, fmaf(-cS.y, cO.y, jv.y));
            jv.z = fmaf(aS.z, bO.z, fmaf(-cS.z, cO.z, jv.z));
            jv.w = fmaf(aS.w, bO.w, fmaf(-cS.w, cO.w, jv.w));
        }
        j2 += (jv.x + jv.y) + (jv.z + jv.w);

        m0[0] = m1[0]; m0[1] = m1[1];
        m1[0] = m2[0]; m1[1] = m2[1];
    }

    // ---- reduction (J2 carries symmetry factor 2) ----
    float vals[7] = { accB[0], accB[1], accA[0], accA[1], accC[0], accC[1], 2.f * j2 };
    #pragma unroll
    for (int q = 0; q < 7; q++) {
        float v = vals[q];
        #pragma unroll
        for (int off = 16; off; off >>= 1) v += __shfl_xor_sync(FULLMASK, v, off);
        vals[q] = v;
    }
    __syncthreads();
    if (tx == 0) {
        #pragma unroll
        for (int q = 0; q < 7; q++) s_red[wid*8 + q] = vals[q];
    }
    __syncthreads();
    if (tid < 14) {
        const int g = tid / 7, q = tid % 7;
        float s = 0.f;
        #pragma unroll
        for (int w = 0; w < 8; w++) s += s_red[(8*g + w)*8 + q];
        double* dst;
        if (q < 2)       dst = &g_acc[b*4 + 2*g + q];
        else if (q < 4)  dst = &g_acc[8 + b*4 + 2*g + (q - 2)];
        else if (q < 6)  dst = &g_acc[16 + b*4 + 2*g + (q - 4)];
        else             dst = &g_acc[24];
        atomicAdd(dst, (double)s);
        __threadfence();
    }
    __syncthreads();

    // ---- last of 256 blocks finalizes + resets for next graph replay ----
    if (tid == 0) {
        unsigned old = atomicAdd(&g_sem, 1u);
        if (old == 255u) {
            volatile double* ga = g_acc;
            double j1 = 0.0;
            #pragma unroll
            for (int i = 0; i < 8; i++) {
                double Bv = ga[i], Av = ga[8 + i], Cv = ga[16 + i];
                j1 += Cv - Av * Av / Bv;
            }
            const double inv = 1.0 / 4194304.0;
            out[0] = (float)(j1 * inv + 0.0008 * ga[24] * inv);
            #pragma unroll
            for (int i = 0; i < 25; i++) g_acc[i] = 0.0;
            g_sem = 0u;
        }
    }
}

extern "C" void kernel_launch(void* const* d_in, const int* in_sizes, int n_in,
                              void* d_out, int out_size) {
    const float* ypred = (const float*)d_in[0];
    const float* image = (const float*)d_in[1];
    if (n_in >= 2 && in_sizes[0] < in_sizes[1]) {  // robustness to input order
        ypred = (const float*)d_in[1];
        image = (const float*)d_in[0];
    }
    cudaFuncSetAttribute(rfcm_kernel, cudaFuncAttributeMaxDynamicSharedMemorySize,
                         SMEM_BYTES);
    rfcm_kernel<<<dim3(16, 8, 2), dim3(32, 8, 2), SMEM_BYTES>>>(ypred, image, (float*)d_out);
}